// round 5
// baseline (speedup 1.0000x reference)
#include <cuda_runtime.h>
#include <cfloat>
#include <cstdint>

// Problem constants: x [64,32,32,256] -> 65536 x 256, codebook 1024 x 256.
#define N_ROWS  65536
#define DIM     256
#define KCODES  1024
#define RN      128     // rows per block tile
#define CK      128     // codes per chunk
#define NCHUNK  (KCODES / CK)
#define DK      8       // depth slice
#define NDS     (DIM / DK)
#define TS      132     // xs row stride (floats)
#define S2      260     // es_dup row stride (floats): 1040B, 16B-aligned, %32 = 4
#define NTHREADS 256

__device__ float g_enorm[KCODES];

__device__ __forceinline__ uint32_t smem_u32(const void* p) {
    uint32_t a;
    asm("{ .reg .u64 t; cvta.to.shared.u64 t, %1; cvt.u32.u64 %0, t; }" : "=r"(a) : "l"(p));
    return a;
}

__global__ void enorm_kernel(const float* __restrict__ cb) {
    int code = blockIdx.x;
    int t = threadIdx.x;              // 64 threads, one float4 each
    const float4* row = reinterpret_cast<const float4*>(cb + (size_t)code * DIM);
    float4 v = row[t];
    float s = v.x * v.x + v.y * v.y + v.z * v.z + v.w * v.w;
    #pragma unroll
    for (int o = 16; o > 0; o >>= 1) s += __shfl_down_sync(0xffffffffu, s, o);
    __shared__ float ws[2];
    if ((t & 31) == 0) ws[t >> 5] = s;
    __syncthreads();
    if (t == 0) g_enorm[code] = ws[0] + ws[1];
}

__global__ __launch_bounds__(NTHREADS, 2)
void vq_kernel(const float* __restrict__ x, const float* __restrict__ cb,
               float* __restrict__ outq, float* __restrict__ outidx, int has_idx)
{
    __shared__ alignas(16) float xs[2][DK][TS];      // x tile, dim-major: [dd][row]
    __shared__ alignas(16) float es[2][DK][S2];      // codebook tile, DUPLICATED: [dd][2*code+{0,1}]
    __shared__ float snorm[KCODES];
    __shared__ int   sIdx[RN];

    const int tid = threadIdx.x;
    const int tx = tid & 15;          // code group
    const int ty = tid >> 4;          // row group (8 rows: ty*8..+7)
    const int r0 = blockIdx.x * RN;

    const uint32_t xs_s = smem_u32(&xs[0][0][0]);
    const uint32_t es_s = smem_u32(&es[0][0][0]);

    // stage-load mapping: 128 rows/codes x 2 float4 per 8-dim slice -> 256 threads, 1 float4 each
    const int row0 = tid >> 1;        // 0..127 (row for xs, code for es)
    const int q0   = tid & 1;         // which float4 of the 8-dim slice

    for (int i = tid; i < KCODES; i += NTHREADS) snorm[i] = g_enorm[i];

    float minv[8];
    int   mini[8];
    #pragma unroll
    for (int i = 0; i < 8; i++) { minv[i] = FLT_MAX; mini[i] = 0; }

    #pragma unroll 1
    for (int kc = 0; kc < NCHUNK; kc++) {
        // acc2[i][jc]: rows (ty*8+2i, ty*8+2i+1) x code (cbase + 32*(jc>>1) + 2*tx + (jc&1))
        uint64_t acc2[4][8];
        #pragma unroll
        for (int i = 0; i < 4; i++)
            #pragma unroll
            for (int j = 0; j < 8; j++) acc2[i][j] = 0ull;

        const int cbase = kc * CK;

        __syncthreads();  // protect smem reuse across chunks

        // --- prologue: load stage 0 into buffer 0 ---
        {
            const float4 vx = *reinterpret_cast<const float4*>(&x[(size_t)(r0 + row0) * DIM + q0 * 4]);
            const float4 ve = *reinterpret_cast<const float4*>(&cb[(size_t)(cbase + row0) * DIM + q0 * 4]);
            #pragma unroll
            for (int k = 0; k < 4; k++) {
                const float vxk = (&vx.x)[k];
                xs[0][q0 * 4 + k][row0] = vxk;
            }
            #pragma unroll
            for (int k = 0; k < 4; k++) {
                const float vek = (&ve.x)[k];
                const uint32_t ad = es_s + ((q0 * 4 + k) * S2 + 2 * row0) * 4;
                asm volatile("st.shared.v2.f32 [%0], {%1, %1};" :: "r"(ad), "f"(vek) : "memory");
            }
        }
        __syncthreads();

        int buf = 0;
        #pragma unroll 1
        for (int ds = 0; ds < NDS; ds++) {
            float4 px, pe;
            if (ds < NDS - 1) {
                const int d0 = (ds + 1) * DK;
                px = *reinterpret_cast<const float4*>(&x[(size_t)(r0 + row0) * DIM + d0 + q0 * 4]);
                pe = *reinterpret_cast<const float4*>(&cb[(size_t)(cbase + row0) * DIM + d0 + q0 * 4]);
            }

            // --- compute DK depth steps: zero-MOV packed FMA ---
            const uint32_t xb = xs_s + (uint32_t)buf * (DK * TS * 4) + (uint32_t)(ty * 32);
            const uint32_t eb = es_s + (uint32_t)buf * (DK * S2 * 4) + (uint32_t)(tx * 16);
            #pragma unroll
            for (int dd = 0; dd < DK; dd++) {
                uint64_t av[4];   // row pairs (2i, 2i+1)
                uint64_t bv[8];   // code dup-pairs, codes 32*jj + 2*tx + p
                const uint32_t xa = xb + (uint32_t)(dd * TS * 4);
                const uint32_t ea = eb + (uint32_t)(dd * S2 * 4);
                asm("ld.shared.v2.b64 {%0, %1}, [%2];" : "=l"(av[0]), "=l"(av[1]) : "r"(xa));
                asm("ld.shared.v2.b64 {%0, %1}, [%2];" : "=l"(av[2]), "=l"(av[3]) : "r"(xa + 16));
                asm("ld.shared.v2.b64 {%0, %1}, [%2];" : "=l"(bv[0]), "=l"(bv[1]) : "r"(ea));
                asm("ld.shared.v2.b64 {%0, %1}, [%2];" : "=l"(bv[2]), "=l"(bv[3]) : "r"(ea + 256));
                asm("ld.shared.v2.b64 {%0, %1}, [%2];" : "=l"(bv[4]), "=l"(bv[5]) : "r"(ea + 512));
                asm("ld.shared.v2.b64 {%0, %1}, [%2];" : "=l"(bv[6]), "=l"(bv[7]) : "r"(ea + 768));
                #pragma unroll
                for (int j = 0; j < 8; j++)
                    #pragma unroll
                    for (int i = 0; i < 4; i++)
                        asm("fma.rn.f32x2 %0, %1, %2, %0;" : "+l"(acc2[i][j]) : "l"(av[i]), "l"(bv[j]));
            }

            if (ds < NDS - 1) {
                const int nb = buf ^ 1;
                #pragma unroll
                for (int k = 0; k < 4; k++) xs[nb][q0 * 4 + k][row0] = (&px.x)[k];
                #pragma unroll
                for (int k = 0; k < 4; k++) {
                    const float vek = (&pe.x)[k];
                    const uint32_t ad = es_s + (uint32_t)nb * (DK * S2 * 4)
                                      + ((q0 * 4 + k) * S2 + 2 * row0) * 4;
                    asm volatile("st.shared.v2.f32 [%0], {%1, %1};" :: "r"(ad), "f"(vek) : "memory");
                }
                __syncthreads();
                buf = nb;
            }
        }

        // --- chunk epilogue: dist = ||e||^2 - 2 x.e ; running argmin (codes ascending per thread) ---
        #pragma unroll
        for (int jj = 0; jj < 4; jj++) {
            #pragma unroll
            for (int p = 0; p < 2; p++) {
                const int code = cbase + 32 * jj + 2 * tx + p;
                const float en = snorm[code];
                #pragma unroll
                for (int i = 0; i < 4; i++) {
                    float lo, hi;
                    asm("mov.b64 {%0, %1}, %2;" : "=f"(lo), "=f"(hi) : "l"(acc2[i][jj * 2 + p]));
                    const float d0 = en - 2.0f * lo;   // row ty*8 + 2i
                    const float d1 = en - 2.0f * hi;   // row ty*8 + 2i+1
                    if (d0 < minv[2 * i])     { minv[2 * i]     = d0; mini[2 * i]     = code; }
                    if (d1 < minv[2 * i + 1]) { minv[2 * i + 1] = d1; mini[2 * i + 1] = code; }
                }
            }
        }
    }

    // --- reduce across the 16 code threads sharing each row (prefer smaller idx on ties) ---
    #pragma unroll
    for (int i = 0; i < 8; i++) {
        float v = minv[i];
        int   id = mini[i];
        #pragma unroll
        for (int o = 8; o > 0; o >>= 1) {
            const float ov = __shfl_down_sync(0xffffffffu, v, o, 16);
            const int   oi = __shfl_down_sync(0xffffffffu, id, o, 16);
            if (ov < v || (ov == v && oi < id)) { v = ov; id = oi; }
        }
        if (tx == 0) sIdx[ty * 8 + i] = id;
    }
    __syncthreads();

    // --- gather e[idx] rows (codebook is L2-resident) and write quantized output ---
    const float4* cb4  = reinterpret_cast<const float4*>(cb);
    float4*       out4 = reinterpret_cast<float4*>(outq);
    #pragma unroll 4
    for (int f = tid; f < RN * DIM / 4; f += NTHREADS) {
        const int row  = f >> 6;   // 64 float4 per row
        const int c    = f & 63;
        const int code = sIdx[row];
        out4[(size_t)(r0 + row) * (DIM / 4) + c] = cb4[(size_t)code * (DIM / 4) + c];
    }
    if (has_idx && tid < RN) outidx[r0 + tid] = (float)sIdx[tid];
}

extern "C" void kernel_launch(void* const* d_in, const int* in_sizes, int n_in,
                              void* d_out, int out_size) {
    const float* x  = (const float*)d_in[0];   // [65536, 256] flattened
    const float* cb = (const float*)d_in[1];   // [1024, 256]
    float* outq = (float*)d_out;

    const int qElems = N_ROWS * DIM;
    const int has_idx = (out_size >= qElems + N_ROWS) ? 1 : 0;
    float* outidx = outq + qElems;

    enorm_kernel<<<KCODES, 64>>>(cb);
    vq_kernel<<<N_ROWS / RN, NTHREADS>>>(x, cb, outq, outidx, has_idx);
}

// round 6
// speedup vs baseline: 1.1119x; 1.1119x over previous
#include <cuda_runtime.h>
#include <cfloat>
#include <cstdint>

// Problem: x [65536, 256] fp32, codebook [1024, 256] fp32. Nearest code per row.
#define N_ROWS  65536
#define DIM     256
#define KCODES  1024
#define RN      128     // rows per CTA
#define CN      128     // codes per chunk
#define NCHUNK  (KCODES / CN)
#define KS      16      // dims per stage
#define NST     (DIM / KS)
#define NTHREADS 256

// smem byte offsets (tile regions hold 2 buffers of 512 float4 = 8192B each)
#define OFF_AH     0
#define OFF_AL     16384
#define OFF_BH     32768
#define OFF_BL     49152
#define OFF_SNORM  65536
#define OFF_SREDV  69632
#define OFF_SREDI  70656
#define OFF_SIDX   71680
#define SMEM_BYTES 72192
#define BUFSTRIDE  8192

__device__ float g_enorm[KCODES];

__device__ __forceinline__ uint32_t smem_u32(const void* p) {
    uint32_t a;
    asm("{ .reg .u64 t; cvta.to.shared.u64 t, %1; cvt.u32.u64 %0, t; }" : "=r"(a) : "l"(p));
    return a;
}

// fp32 -> tf32 hi/lo split
__device__ __forceinline__ void split1(float v, uint32_t& h, uint32_t& l) {
    uint32_t hb; asm("cvt.rna.tf32.f32 %0, %1;" : "=r"(hb) : "f"(v));
    float lf = v - __uint_as_float(hb);
    uint32_t lb; asm("cvt.rna.tf32.f32 %0, %1;" : "=r"(lb) : "f"(lf));
    h = hb; l = lb;
}
__device__ __forceinline__ void split4(float4 v, uint4& h, uint4& l) {
    split1(v.x, h.x, l.x); split1(v.y, h.y, l.y);
    split1(v.z, h.z, l.z); split1(v.w, h.w, l.w);
}

__device__ __forceinline__ void ldm4(uint32_t* r, uint32_t addr) {
    asm volatile("ldmatrix.sync.aligned.m8n8.x4.shared.b16 {%0,%1,%2,%3}, [%4];"
                 : "=r"(r[0]), "=r"(r[1]), "=r"(r[2]), "=r"(r[3]) : "r"(addr));
}

__device__ __forceinline__ void mma8(float* c, const uint32_t* a, uint32_t b0, uint32_t b1) {
    asm volatile(
        "mma.sync.aligned.m16n8k8.row.col.f32.tf32.tf32.f32 "
        "{%0,%1,%2,%3}, {%4,%5,%6,%7}, {%8,%9}, {%0,%1,%2,%3};"
        : "+f"(c[0]), "+f"(c[1]), "+f"(c[2]), "+f"(c[3])
        : "r"(a[0]), "r"(a[1]), "r"(a[2]), "r"(a[3]), "r"(b0), "r"(b1));
}

__global__ void enorm_kernel(const float* __restrict__ cb) {
    int code = blockIdx.x;
    int t = threadIdx.x;  // 64 threads, one float4 each
    const float4* row = reinterpret_cast<const float4*>(cb + (size_t)code * DIM);
    float4 v = row[t];
    float s = v.x * v.x + v.y * v.y + v.z * v.z + v.w * v.w;
    #pragma unroll
    for (int o = 16; o > 0; o >>= 1) s += __shfl_down_sync(0xffffffffu, s, o);
    __shared__ float ws[2];
    if ((t & 31) == 0) ws[t >> 5] = s;
    __syncthreads();
    if (t == 0) g_enorm[code] = ws[0] + ws[1];
}

__global__ __launch_bounds__(NTHREADS, 1)
void vq_kernel(const float* __restrict__ x, const float* __restrict__ cb,
               float* __restrict__ outq, float* __restrict__ outidx, int has_idx)
{
    extern __shared__ char sm[];
    const uint32_t sb = smem_u32(sm);
    const int tid  = threadIdx.x;
    const int lane = tid & 31;
    const int wid  = tid >> 5;
    const int wm   = wid & 3;    // warp row block: rows wm*32..+31
    const int wn   = wid >> 2;   // warp code block: codes wn*64..+63 within chunk
    const int r0   = blockIdx.x * RN;

    float* snorm = (float*)(sm + OFF_SNORM);
    for (int i = tid; i < KCODES; i += NTHREADS) snorm[i] = g_enorm[i];

    // stage-load mapping: float4 f -> (row, dim-quad). Blocked tile layout: tile=f/8, r=f%8.
    const int f1 = tid, f2 = tid + 256;
    const int rowA1 = (f1 >> 5) * 8 + (f1 & 7), kb1 = (f1 >> 3) & 3;
    const int rowA2 = (f2 >> 5) * 8 + (f2 & 7), kb2 = (f2 >> 3) & 3;
    const uint32_t so1 = (uint32_t)f1 * 16, so2 = (uint32_t)f2 * 16;

    // ldmatrix lane offsets (j = lane/8 selects tile, r = lane%8 selects row)
    const uint32_t aoff = ((lane >> 3) & 1) * 512 + (lane >> 4) * 128 + (lane & 7) * 16;
    const uint32_t boff = (lane >> 4) * 512 + ((lane >> 3) & 1) * 128 + (lane & 7) * 16;

    float minv[4];
    int   mini[4];
    #pragma unroll
    for (int i = 0; i < 4; i++) { minv[i] = FLT_MAX; mini[i] = 0; }

    #pragma unroll 1
    for (int c = 0; c < NCHUNK; c++) {
        const int cbase = c * CN;
        float acc[2][8][4];
        #pragma unroll
        for (int mt = 0; mt < 2; mt++)
            #pragma unroll
            for (int nt = 0; nt < 8; nt++)
                #pragma unroll
                for (int q = 0; q < 4; q++) acc[mt][nt][q] = 0.0f;

        __syncthreads();   // previous chunk fully done with tiles

        // --- stage 0 load ---
        {
            const float4 a1 = *(const float4*)(x  + (size_t)(r0 + rowA1) * DIM + kb1 * 4);
            const float4 a2 = *(const float4*)(x  + (size_t)(r0 + rowA2) * DIM + kb2 * 4);
            const float4 b1 = *(const float4*)(cb + (size_t)(cbase + rowA1) * DIM + kb1 * 4);
            const float4 b2 = *(const float4*)(cb + (size_t)(cbase + rowA2) * DIM + kb2 * 4);
            uint4 h, l;
            split4(a1, h, l); *(uint4*)(sm + OFF_AH + so1) = h; *(uint4*)(sm + OFF_AL + so1) = l;
            split4(a2, h, l); *(uint4*)(sm + OFF_AH + so2) = h; *(uint4*)(sm + OFF_AL + so2) = l;
            split4(b1, h, l); *(uint4*)(sm + OFF_BH + so1) = h; *(uint4*)(sm + OFF_BL + so1) = l;
            split4(b2, h, l); *(uint4*)(sm + OFF_BH + so2) = h; *(uint4*)(sm + OFF_BL + so2) = l;
        }
        __syncthreads();

        int buf = 0;
        #pragma unroll 1
        for (int s = 0; s < NST; s++) {
            float4 pa1, pa2, pb1, pb2;
            if (s < NST - 1) {
                const int d0 = (s + 1) * KS;
                pa1 = *(const float4*)(x  + (size_t)(r0 + rowA1) * DIM + d0 + kb1 * 4);
                pa2 = *(const float4*)(x  + (size_t)(r0 + rowA2) * DIM + d0 + kb2 * 4);
                pb1 = *(const float4*)(cb + (size_t)(cbase + rowA1) * DIM + d0 + kb1 * 4);
                pb2 = *(const float4*)(cb + (size_t)(cbase + rowA2) * DIM + d0 + kb2 * 4);
            }

            const uint32_t ahb = sb + OFF_AH + (uint32_t)buf * BUFSTRIDE;
            const uint32_t alb = sb + OFF_AL + (uint32_t)buf * BUFSTRIDE;
            const uint32_t bhb = sb + OFF_BH + (uint32_t)buf * BUFSTRIDE;
            const uint32_t blb = sb + OFF_BL + (uint32_t)buf * BUFSTRIDE;

            #pragma unroll
            for (int kk = 0; kk < 2; kk++) {
                uint32_t ah[2][4], al[2][4];
                #pragma unroll
                for (int mt = 0; mt < 2; mt++) {
                    const uint32_t tb = (uint32_t)((wm * 4 + mt * 2) * 512 + kk * 256);
                    ldm4(ah[mt], ahb + tb + aoff);
                    ldm4(al[mt], alb + tb + aoff);
                }
                #pragma unroll
                for (int np = 0; np < 4; np++) {
                    uint32_t bh[4], bl[4];
                    const uint32_t tb = (uint32_t)((wn * 8 + np * 2) * 512 + kk * 256);
                    ldm4(bh, bhb + tb + boff);
                    ldm4(bl, blb + tb + boff);
                    #pragma unroll
                    for (int mt = 0; mt < 2; mt++) {
                        float* c0 = acc[mt][np * 2];
                        mma8(c0, ah[mt], bh[0], bh[1]);   // hh
                        mma8(c0, ah[mt], bl[0], bl[1]);   // hl
                        mma8(c0, al[mt], bh[0], bh[1]);   // lh
                        mma8(c0, al[mt], bl[0], bl[1]);   // ll
                        float* c1 = acc[mt][np * 2 + 1];
                        mma8(c1, ah[mt], bh[2], bh[3]);
                        mma8(c1, ah[mt], bl[2], bl[3]);
                        mma8(c1, al[mt], bh[2], bh[3]);
                        mma8(c1, al[mt], bl[2], bl[3]);
                    }
                }
            }

            if (s < NST - 1) {
                const int nb = buf ^ 1;
                uint4 h, l;
                split4(pa1, h, l);
                *(uint4*)(sm + OFF_AH + nb * BUFSTRIDE + so1) = h;
                *(uint4*)(sm + OFF_AL + nb * BUFSTRIDE + so1) = l;
                split4(pa2, h, l);
                *(uint4*)(sm + OFF_AH + nb * BUFSTRIDE + so2) = h;
                *(uint4*)(sm + OFF_AL + nb * BUFSTRIDE + so2) = l;
                split4(pb1, h, l);
                *(uint4*)(sm + OFF_BH + nb * BUFSTRIDE + so1) = h;
                *(uint4*)(sm + OFF_BL + nb * BUFSTRIDE + so1) = l;
                split4(pb2, h, l);
                *(uint4*)(sm + OFF_BH + nb * BUFSTRIDE + so2) = h;
                *(uint4*)(sm + OFF_BL + nb * BUFSTRIDE + so2) = l;
                __syncthreads();
                buf = nb;
            }
        }

        // --- chunk epilogue: dist = ||e||^2 - 2 x.e ; running argmin (codes ascending per thread) ---
        #pragma unroll
        for (int nt = 0; nt < 8; nt++) {
            const int code0 = cbase + wn * 64 + nt * 8 + 2 * (lane & 3);
            const float en0 = snorm[code0];
            const float en1 = snorm[code0 + 1];
            #pragma unroll
            for (int mt = 0; mt < 2; mt++) {
                const float* a = acc[mt][nt];
                const int s0 = mt * 2, s1 = mt * 2 + 1;
                float d;
                d = en0 - 2.0f * a[0]; if (d < minv[s0]) { minv[s0] = d; mini[s0] = code0; }
                d = en1 - 2.0f * a[1]; if (d < minv[s0]) { minv[s0] = d; mini[s0] = code0 + 1; }
                d = en0 - 2.0f * a[2]; if (d < minv[s1]) { minv[s1] = d; mini[s1] = code0; }
                d = en1 - 2.0f * a[3]; if (d < minv[s1]) { minv[s1] = d; mini[s1] = code0 + 1; }
            }
        }
    }

    // --- reduce: lanes 4g..4g+3 share rows; tie -> smaller code ---
    float* sredv = (float*)(sm + OFF_SREDV);
    int*   sredi = (int*)(sm + OFF_SREDI);
    #pragma unroll
    for (int sl = 0; sl < 4; sl++) {
        float v = minv[sl];
        int   id = mini[sl];
        #pragma unroll
        for (int o = 1; o <= 2; o <<= 1) {
            const float ov = __shfl_xor_sync(0xffffffffu, v, o);
            const int   oi = __shfl_xor_sync(0xffffffffu, id, o);
            if (ov < v || (ov == v && oi < id)) { v = ov; id = oi; }
        }
        if ((lane & 3) == 0) {
            const int rowl = wm * 32 + (sl >> 1) * 16 + (sl & 1) * 8 + (lane >> 2);
            sredv[wn * 128 + rowl] = v;
            sredi[wn * 128 + rowl] = id;
        }
    }
    __syncthreads();
    int* sIdx = (int*)(sm + OFF_SIDX);
    if (tid < 128) {
        float v0 = sredv[tid];       int i0 = sredi[tid];
        const float v1 = sredv[128 + tid];
        const int   i1 = sredi[128 + tid];
        if (v1 < v0 || (v1 == v0 && i1 < i0)) { v0 = v1; i0 = i1; }
        sIdx[tid] = i0;
    }
    __syncthreads();

    // --- gather e[idx] rows and write outputs ---
    const float4* cb4  = reinterpret_cast<const float4*>(cb);
    float4*       out4 = reinterpret_cast<float4*>(outq);
    #pragma unroll 4
    for (int f = tid; f < RN * DIM / 4; f += NTHREADS) {
        const int row  = f >> 6;
        const int cc   = f & 63;
        const int code = sIdx[row];
        out4[(size_t)(r0 + row) * (DIM / 4) + cc] = cb4[(size_t)code * (DIM / 4) + cc];
    }
    if (has_idx && tid < RN) outidx[r0 + tid] = (float)sIdx[tid];
}

extern "C" void kernel_launch(void* const* d_in, const int* in_sizes, int n_in,
                              void* d_out, int out_size) {
    const float* x  = (const float*)d_in[0];   // [65536, 256]
    const float* cb = (const float*)d_in[1];   // [1024, 256]
    float* outq = (float*)d_out;

    const int qElems = N_ROWS * DIM;
    const int has_idx = (out_size >= qElems + N_ROWS) ? 1 : 0;
    float* outidx = outq + qElems;

    cudaFuncSetAttribute(vq_kernel, cudaFuncAttributeMaxDynamicSharedMemorySize, SMEM_BYTES);

    enorm_kernel<<<KCODES, 64>>>(cb);
    vq_kernel<<<N_ROWS / RN, NTHREADS, SMEM_BYTES>>>(x, cb, outq, outidx, has_idx);
}